// round 3
// baseline (speedup 1.0000x reference)
#include <cuda_runtime.h>

#define NN 20000
#define NE 320000
#define NB 32
#define HDIM 64
#define HC 256   // H*C
#define NH 4
#define NL 3

// ---------------- scratch (device globals; no allocation allowed) ----------
__device__ int   g_deg[NN];
__device__ int   g_rowptr[NN + 1];
__device__ int   g_fill[NN];
__device__ int   g_csrc[NE];
__device__ int   g_ceid[NE];
__device__ float g_h0[NN * HDIM];
__device__ float g_h1[NN * HDIM];
__device__ float g_xp[NN * HC];
__device__ float g_as[NN * NH];
__device__ float g_ad[NN * NH];
__device__ float g_aede[NE * 12];   // per-edge attention logits, [E][l*4+h]
__device__ float g_aeds[NN * 12];   // self-loop logits (sum, then /deg in place)
__device__ float g_weatt[HDIM * 12];
__device__ float g_pool[NB * HDIM];
__device__ int   g_cnt[NB];

__device__ __forceinline__ float lrelu(float x) { return x > 0.f ? x : 0.2f * x; }

// ---------------- preprocessing ---------------------------------------------
__global__ void hist_kernel(const int* __restrict__ dst) {
    int e = blockIdx.x * blockDim.x + threadIdx.x;
    if (e < NE) atomicAdd(&g_deg[dst[e]], 1);
}

__global__ __launch_bounds__(1024) void scan_kernel() {
    __shared__ int s[1024];
    __shared__ int carry;
    int t = threadIdx.x;
    if (t == 0) { carry = 0; g_rowptr[0] = 0; }
    __syncthreads();
    for (int base = 0; base < NN; base += 1024) {
        int i = base + t;
        int v = (i < NN) ? g_deg[i] : 0;
        s[t] = v;
        __syncthreads();
        #pragma unroll
        for (int off = 1; off < 1024; off <<= 1) {
            int tv = (t >= off) ? s[t - off] : 0;
            __syncthreads();
            s[t] += tv;
            __syncthreads();
        }
        if (i < NN) g_rowptr[i + 1] = carry + s[t];
        __syncthreads();
        if (t == 0) carry += s[1023];
        __syncthreads();
    }
}

__global__ void scatter_kernel(const int* __restrict__ src, const int* __restrict__ dst) {
    int e = blockIdx.x * blockDim.x + threadIdx.x;
    if (e >= NE) return;
    int d = dst[e];
    int p = atomicAdd(&g_fill[d], 1);
    int pos = g_rowptr[d] + p;
    g_csrc[pos] = src[e];
    g_ceid[pos] = e;
}

// we_att[d*12 + l*4 + h] = sum_c lin_eW[l][d][h*64+c] * att_e[l][h][c]
__global__ void weatt_kernel(const float* __restrict__ lin_eW, const float* __restrict__ att_e) {
    int idx = blockIdx.x * blockDim.x + threadIdx.x;  // 3 blocks x 256
    if (idx >= NL * HDIM * NH) return;
    int l = idx >> 8;
    int rem = idx & 255;
    int d = rem >> 2;
    int h = rem & 3;
    const float* w = lin_eW + l * HDIM * HC + d * HC + h * 64;
    const float* a = att_e + l * NH * 64 + h * 64;
    float s = 0.f;
    #pragma unroll
    for (int c = 0; c < 64; c++) s += w[c] * a[c];
    g_weatt[d * 12 + l * 4 + h] = s;
}

// ---------------- embeddings ------------------------------------------------
__global__ void node_emb_kernel(const float* __restrict__ x, const float* __restrict__ W,
                                const float* __restrict__ b) {
    int idx = blockIdx.x * blockDim.x + threadIdx.x;
    if (idx >= NN * HDIM) return;
    int n = idx >> 6, c = idx & 63;
    float v = x[n * 3 + 0] * W[c] + x[n * 3 + 1] * W[64 + c] + x[n * 3 + 2] * W[128 + c] + b[c];
    g_h0[idx] = fmaxf(v, 0.f);
}

__global__ __launch_bounds__(256) void edge_emb_kernel(const float* __restrict__ eattr,
                                                       const int* __restrict__ dst,
                                                       const float* __restrict__ eemb_W,
                                                       const float* __restrict__ eemb_b) {
    __shared__ float sW[256];
    __shared__ float sb[64];
    __shared__ float sA[HDIM * 12];
    int t = threadIdx.x;
    if (t < 256) sW[t] = eemb_W[t];
    if (t < 64) sb[t] = eemb_b[t];
    for (int i = t; i < HDIM * 12; i += 256) sA[i] = g_weatt[i];
    __syncthreads();

    int e = blockIdx.x * blockDim.x + t;
    if (e >= NE) return;
    float4 a = *(const float4*)&eattr[e * 4];
    int dn = dst[e];
    float aed[12];
    #pragma unroll
    for (int o = 0; o < 12; o++) aed[o] = 0.f;
    #pragma unroll 4
    for (int d = 0; d < 64; d++) {
        float ea = a.x * sW[d] + a.y * sW[64 + d] + a.z * sW[128 + d] + a.w * sW[192 + d] + sb[d];
        ea = fmaxf(ea, 0.f);
        #pragma unroll
        for (int o = 0; o < 12; o++) aed[o] += ea * sA[d * 12 + o];
    }
    #pragma unroll
    for (int o = 0; o < 12; o++) {
        g_aede[e * 12 + o] = aed[o];
        atomicAdd(&g_aeds[dn * 12 + o], aed[o]);
    }
}

__global__ void selfdiv_kernel() {
    int i = blockIdx.x * blockDim.x + threadIdx.x;
    if (i >= NN * 12) return;
    float dg = fmaxf((float)g_deg[i / 12], 1.f);
    g_aeds[i] = g_aeds[i] / dg;
}

// ---------------- per-layer GEMM: xp = h @ W  (20000x64 @ 64x256) -----------
__global__ __launch_bounds__(256) void gemm_kernel(const float* __restrict__ hin,
                                                   const float* __restrict__ W) {
    __shared__ float Hs[64][65];
    __shared__ float Ws[64][64];
    int n0 = blockIdx.x * 64;
    int c0 = blockIdx.y * 64;
    int tid = threadIdx.x;
    {
        int r = tid >> 4, q = tid & 15;
        #pragma unroll
        for (int rr = 0; rr < 64; rr += 16) {
            int row = r + rr;
            float4 v = make_float4(0.f, 0.f, 0.f, 0.f);
            if (n0 + row < NN) v = *(const float4*)&hin[(n0 + row) * HDIM + q * 4];
            Hs[row][q * 4 + 0] = v.x; Hs[row][q * 4 + 1] = v.y;
            Hs[row][q * 4 + 2] = v.z; Hs[row][q * 4 + 3] = v.w;
            float4 w = *(const float4*)&W[row * HC + c0 + q * 4];
            *(float4*)&Ws[row][q * 4] = w;
        }
    }
    __syncthreads();
    int ty = tid >> 4, tx = tid & 15;
    float acc[4][4];
    #pragma unroll
    for (int i = 0; i < 4; i++)
        #pragma unroll
        for (int j = 0; j < 4; j++) acc[i][j] = 0.f;
    #pragma unroll 8
    for (int k = 0; k < 64; k++) {
        float a0 = Hs[ty * 4 + 0][k], a1 = Hs[ty * 4 + 1][k];
        float a2 = Hs[ty * 4 + 2][k], a3 = Hs[ty * 4 + 3][k];
        float4 w = *(float4*)&Ws[k][tx * 4];
        acc[0][0] += a0 * w.x; acc[0][1] += a0 * w.y; acc[0][2] += a0 * w.z; acc[0][3] += a0 * w.w;
        acc[1][0] += a1 * w.x; acc[1][1] += a1 * w.y; acc[1][2] += a1 * w.z; acc[1][3] += a1 * w.w;
        acc[2][0] += a2 * w.x; acc[2][1] += a2 * w.y; acc[2][2] += a2 * w.z; acc[2][3] += a2 * w.w;
        acc[3][0] += a3 * w.x; acc[3][1] += a3 * w.y; acc[3][2] += a3 * w.z; acc[3][3] += a3 * w.w;
    }
    #pragma unroll
    for (int i = 0; i < 4; i++) {
        int row = n0 + ty * 4 + i;
        if (row < NN)
            *(float4*)&g_xp[row * HC + c0 + tx * 4] =
                make_float4(acc[i][0], acc[i][1], acc[i][2], acc[i][3]);
    }
}

// a_s[n,h], a_d[n,h] — one warp per node
__global__ void attnd_kernel(const float* __restrict__ att_src, const float* __restrict__ att_dst) {
    int warp = (blockIdx.x * blockDim.x + threadIdx.x) >> 5;
    if (warp >= NN) return;
    int lane = threadIdx.x & 31;
    float xv[8];
    #pragma unroll
    for (int k = 0; k < 8; k++) xv[k] = g_xp[warp * HC + lane + 32 * k];
    float s[4], d[4];
    #pragma unroll
    for (int h = 0; h < 4; h++) {
        s[h] = xv[2 * h] * att_src[h * 64 + lane] + xv[2 * h + 1] * att_src[h * 64 + 32 + lane];
        d[h] = xv[2 * h] * att_dst[h * 64 + lane] + xv[2 * h + 1] * att_dst[h * 64 + 32 + lane];
    }
    #pragma unroll
    for (int off = 16; off >= 1; off >>= 1) {
        #pragma unroll
        for (int h = 0; h < 4; h++) {
            s[h] += __shfl_xor_sync(0xffffffffu, s[h], off);
            d[h] += __shfl_xor_sync(0xffffffffu, d[h], off);
        }
    }
    if (lane < 4) {
        g_as[warp * 4 + lane] = s[lane];
        g_ad[warp * 4 + lane] = d[lane];
    }
}

// attention softmax + aggregation + head-mean + bias + relu — one warp per node
__global__ __launch_bounds__(256) void aggr_kernel(const float* __restrict__ conv_b, int layer,
                                                   float* __restrict__ hout) {
    int warp = (blockIdx.x * blockDim.x + threadIdx.x) >> 5;
    if (warp >= NN) return;
    int lane = threadIdx.x & 31;
    int n = warp;
    int beg = g_rowptr[n], end = g_rowptr[n + 1];
    int l4 = layer * 4;

    float4 adv = *(const float4*)&g_ad[n * 4];
    float4 asl = *(const float4*)&g_as[n * 4];
    float4 aes = *(const float4*)&g_aeds[n * 12 + l4];

    float als0 = lrelu(asl.x + adv.x + aes.x);
    float als1 = lrelu(asl.y + adv.y + aes.y);
    float als2 = lrelu(asl.z + adv.z + aes.z);
    float als3 = lrelu(asl.w + adv.w + aes.w);

    float mx0 = als0, mx1 = als1, mx2 = als2, mx3 = als3;
    for (int e = beg + lane; e < end; e += 32) {
        int s = g_csrc[e];
        int id = g_ceid[e];
        float4 av = *(const float4*)&g_as[s * 4];
        float4 ae = *(const float4*)&g_aede[id * 12 + l4];
        mx0 = fmaxf(mx0, lrelu(av.x + adv.x + ae.x));
        mx1 = fmaxf(mx1, lrelu(av.y + adv.y + ae.y));
        mx2 = fmaxf(mx2, lrelu(av.z + adv.z + ae.z));
        mx3 = fmaxf(mx3, lrelu(av.w + adv.w + ae.w));
    }
    #pragma unroll
    for (int off = 16; off >= 1; off >>= 1) {
        mx0 = fmaxf(mx0, __shfl_xor_sync(0xffffffffu, mx0, off));
        mx1 = fmaxf(mx1, __shfl_xor_sync(0xffffffffu, mx1, off));
        mx2 = fmaxf(mx2, __shfl_xor_sync(0xffffffffu, mx2, off));
        mx3 = fmaxf(mx3, __shfl_xor_sync(0xffffffffu, mx3, off));
    }

    // self contribution
    float ex0 = __expf(als0 - mx0), ex1 = __expf(als1 - mx1);
    float ex2 = __expf(als2 - mx2), ex3 = __expf(als3 - mx3);
    float den0 = ex0, den1 = ex1, den2 = ex2, den3 = ex3;
    float acc[8];
    {
        const float* xr = g_xp + n * HC + lane;
        acc[0] = ex0 * xr[0];   acc[1] = ex0 * xr[32];
        acc[2] = ex1 * xr[64];  acc[3] = ex1 * xr[96];
        acc[4] = ex2 * xr[128]; acc[5] = ex2 * xr[160];
        acc[6] = ex3 * xr[192]; acc[7] = ex3 * xr[224];
    }
    for (int e = beg; e < end; e++) {
        int s = g_csrc[e];
        int id = g_ceid[e];
        float4 av = *(const float4*)&g_as[s * 4];
        float4 ae = *(const float4*)&g_aede[id * 12 + l4];
        float e0 = __expf(lrelu(av.x + adv.x + ae.x) - mx0);
        float e1 = __expf(lrelu(av.y + adv.y + ae.y) - mx1);
        float e2 = __expf(lrelu(av.z + adv.z + ae.z) - mx2);
        float e3 = __expf(lrelu(av.w + adv.w + ae.w) - mx3);
        den0 += e0; den1 += e1; den2 += e2; den3 += e3;
        const float* xr = g_xp + s * HC + lane;
        acc[0] += e0 * xr[0];   acc[1] += e0 * xr[32];
        acc[2] += e1 * xr[64];  acc[3] += e1 * xr[96];
        acc[4] += e2 * xr[128]; acc[5] += e2 * xr[160];
        acc[6] += e3 * xr[192]; acc[7] += e3 * xr[224];
    }
    float r0 = acc[0] / den0 + acc[2] / den1 + acc[4] / den2 + acc[6] / den3;
    float r1 = acc[1] / den0 + acc[3] / den1 + acc[5] / den2 + acc[7] / den3;
    hout[n * HDIM + lane]      = fmaxf(0.25f * r0 + conv_b[lane], 0.f);
    hout[n * HDIM + lane + 32] = fmaxf(0.25f * r1 + conv_b[lane + 32], 0.f);
}

// ---------------- pooling + head MLP ----------------------------------------
__global__ __launch_bounds__(256) void pool_kernel(const float* __restrict__ h,
                                                   const int* __restrict__ batch) {
    __shared__ float ps[NB * HDIM];
    int t = threadIdx.x;
    for (int i = t; i < NB * HDIM; i += 256) ps[i] = 0.f;
    __syncthreads();
    int n = blockIdx.x * 256 + t;
    if (n < NN) {
        int b = batch[n];
        atomicAdd(&g_cnt[b], 1);
        #pragma unroll 4
        for (int i = 0; i < 64; i++) {
            int c = (t + i) & 63;
            atomicAdd(&ps[b * 64 + c], h[n * 64 + c]);
        }
    }
    __syncthreads();
    for (int i = t; i < NB * HDIM; i += 256) atomicAdd(&g_pool[i], ps[i]);
}

__global__ __launch_bounds__(256) void final_kernel(const float* __restrict__ u,
                                                    const float* __restrict__ gW, const float* __restrict__ gb,
                                                    const float* __restrict__ f1W, const float* __restrict__ f1b,
                                                    const float* __restrict__ f2W, const float* __restrict__ f2b,
                                                    float* __restrict__ out) {
    __shared__ float pooled[NB * HDIM];
    __shared__ float ug[NB * HDIM];
    __shared__ float z1[NB * HDIM];
    int t = threadIdx.x;
    for (int i = t; i < NB * HDIM; i += 256) {
        int b = i >> 6, c = i & 63;
        float cnt = fmaxf((float)g_cnt[b], 1.f);
        pooled[i] = g_pool[i] / cnt;
        float s = gb[c];
        #pragma unroll
        for (int k = 0; k < 10; k++) s += u[b * 10 + k] * gW[k * 64 + c];
        ug[i] = fmaxf(s, 0.f);
    }
    __syncthreads();
    for (int i = t; i < NB * HDIM; i += 256) {
        int b = i >> 6, j = i & 63;
        float s = f1b[j];
        #pragma unroll 8
        for (int k = 0; k < 64; k++) s += pooled[b * 64 + k] * f1W[k * 64 + j];
        #pragma unroll 8
        for (int k = 0; k < 64; k++) s += ug[b * 64 + k] * f1W[(64 + k) * 64 + j];
        z1[i] = fmaxf(s, 0.f);
    }
    __syncthreads();
    if (t < NB * 2) {
        int b = t >> 1, o = t & 1;
        float s = f2b[o];
        #pragma unroll 8
        for (int k = 0; k < 64; k++) s += z1[b * 64 + k] * f2W[k * 2 + o];
        out[b * 2 + o] = s;
    }
}

// ---------------- launch ------------------------------------------------------
extern "C" void kernel_launch(void* const* d_in, const int* in_sizes, int n_in,
                              void* d_out, int out_size) {
    const float* x       = (const float*)d_in[0];
    const int*   eidx    = (const int*)d_in[1];
    const float* eattr   = (const float*)d_in[2];
    const float* u       = (const float*)d_in[3];
    const int*   batch   = (const int*)d_in[4];
    const float* node_W  = (const float*)d_in[5];
    const float* node_b  = (const float*)d_in[6];
    const float* eemb_W  = (const float*)d_in[7];
    const float* eemb_b  = (const float*)d_in[8];
    const float* lin_W   = (const float*)d_in[9];
    const float* att_src = (const float*)d_in[10];
    const float* att_dst = (const float*)d_in[11];
    const float* lin_eW  = (const float*)d_in[12];
    const float* att_e   = (const float*)d_in[13];
    const float* conv_b  = (const float*)d_in[14];
    const float* gW      = (const float*)d_in[15];
    const float* gb      = (const float*)d_in[16];
    const float* f1W     = (const float*)d_in[17];
    const float* f1b     = (const float*)d_in[18];
    const float* f2W     = (const float*)d_in[19];
    const float* f2b     = (const float*)d_in[20];
    float* out = (float*)d_out;

    const int* src = eidx;
    const int* dst = eidx + NE;

    void *p_deg, *p_fill, *p_aeds, *p_pool, *p_cnt, *p_h0, *p_h1;
    cudaGetSymbolAddress(&p_deg,  g_deg);
    cudaGetSymbolAddress(&p_fill, g_fill);
    cudaGetSymbolAddress(&p_aeds, g_aeds);
    cudaGetSymbolAddress(&p_pool, g_pool);
    cudaGetSymbolAddress(&p_cnt,  g_cnt);
    cudaGetSymbolAddress(&p_h0,   g_h0);
    cudaGetSymbolAddress(&p_h1,   g_h1);

    cudaMemsetAsync(p_deg,  0, NN * sizeof(int));
    cudaMemsetAsync(p_fill, 0, NN * sizeof(int));
    cudaMemsetAsync(p_aeds, 0, NN * 12 * sizeof(float));
    cudaMemsetAsync(p_pool, 0, NB * HDIM * sizeof(float));
    cudaMemsetAsync(p_cnt,  0, NB * sizeof(int));

    hist_kernel<<<(NE + 255) / 256, 256>>>(dst);
    scan_kernel<<<1, 1024>>>();
    scatter_kernel<<<(NE + 255) / 256, 256>>>(src, dst);
    weatt_kernel<<<3, 256>>>(lin_eW, att_e);
    node_emb_kernel<<<(NN * HDIM + 255) / 256, 256>>>(x, node_W, node_b);
    edge_emb_kernel<<<(NE + 255) / 256, 256>>>(eattr, dst, eemb_W, eemb_b);
    selfdiv_kernel<<<(NN * 12 + 255) / 256, 256>>>();

    float* hbuf0 = (float*)p_h0;
    float* hbuf1 = (float*)p_h1;
    for (int l = 0; l < NL; l++) {
        const float* hin = (l & 1) ? hbuf1 : hbuf0;
        float* hout = (l & 1) ? hbuf0 : hbuf1;
        dim3 ggrid((NN + 63) / 64, HC / 64);
        gemm_kernel<<<ggrid, 256>>>(hin, lin_W + l * HDIM * HC);
        attnd_kernel<<<(NN * 32 + 255) / 256, 256>>>(att_src + l * NH * 64, att_dst + l * NH * 64);
        aggr_kernel<<<(NN * 32 + 255) / 256, 256>>>(conv_b + l * 64, l, hout);
    }
    // after l=2, output is in hbuf1
    pool_kernel<<<(NN + 255) / 256, 256>>>(hbuf1, batch);
    final_kernel<<<1, 256>>>(u, gW, gb, f1W, f1b, f2W, f2b, out);
}

// round 4
// speedup vs baseline: 1.4045x; 1.4045x over previous
#include <cuda_runtime.h>

#define NN 20000
#define NE 320000
#define NB 32
#define HDIM 64
#define HC 256   // H*C
#define NH 4
#define NL 3

// ---------------- scratch (device globals; no allocation allowed) ----------
__device__ int   g_deg[NN];
__device__ int   g_rowptr[NN + 1];
__device__ int   g_fill[NN];
__device__ int   g_csrc[NE];
__device__ int   g_ceid[NE];
__device__ float g_h0[NN * HDIM];
__device__ float g_h1[NN * HDIM];
__device__ float g_xp[NN * HC];
__device__ float g_as[NN * NH];
__device__ float g_ad[NN * NH];
__device__ float g_aede[NE * 12];   // per-edge attention logits, [E][l*4+h]
__device__ float g_aeds[NN * 12];   // self-loop logit sums (divided by deg at read)
__device__ float g_weatt[HDIM * 12];
__device__ float g_pool[NB * HDIM];
__device__ int   g_cnt[NB];

__device__ __forceinline__ float lrelu(float x) { return x > 0.f ? x : 0.2f * x; }

// ---------------- combined pre-kernel ---------------------------------------
// blocks [0,96): weatt warp-per-output (768 warps)
// remaining blocks: hist (E threads), node_emb (N*64 threads), zero aeds/pool/cnt
#define PRE_WEATT_BLOCKS 96
__global__ __launch_bounds__(256) void pre_kernel(const int* __restrict__ dst,
                                                  const float* __restrict__ x,
                                                  const float* __restrict__ node_W,
                                                  const float* __restrict__ node_b,
                                                  const float* __restrict__ lin_eW,
                                                  const float* __restrict__ att_e) {
    if (blockIdx.x < PRE_WEATT_BLOCKS) {
        // weatt: wid in [0,768); out[d*12 + l*4 + h] = sum_c lin_eW[l][d][h*64+c]*att_e[l][h][c]
        int wid = (blockIdx.x * 256 + threadIdx.x) >> 5;
        int lane = threadIdx.x & 31;
        if (wid >= NL * HDIM * NH) return;
        int l = wid >> 8;
        int rem = wid & 255;
        int d = rem >> 2;
        int h = rem & 3;
        const float* w = lin_eW + l * HDIM * HC + d * HC + h * 64;
        const float* a = att_e + l * NH * 64 + h * 64;
        float s = w[lane] * a[lane] + w[32 + lane] * a[32 + lane];
        #pragma unroll
        for (int off = 16; off >= 1; off >>= 1) s += __shfl_xor_sync(0xffffffffu, s, off);
        if (lane == 0) g_weatt[d * 12 + l * 4 + h] = s;
        return;
    }
    int idx = (blockIdx.x - PRE_WEATT_BLOCKS) * 256 + threadIdx.x;
    if (idx < NE) atomicAdd(&g_deg[dst[idx]], 1);
    if (idx < NN * 12) g_aeds[idx] = 0.f;
    if (idx < NB * HDIM) g_pool[idx] = 0.f;
    if (idx < NB) g_cnt[idx] = 0;
    if (idx < NN * HDIM) {
        int n = idx >> 6, c = idx & 63;
        float v = x[n * 3 + 0] * node_W[c] + x[n * 3 + 1] * node_W[64 + c]
                + x[n * 3 + 2] * node_W[128 + c] + node_b[c];
        g_h0[idx] = fmaxf(v, 0.f);
    }
}

// ---------------- scan: single block, 20 elements per thread ---------------
__global__ __launch_bounds__(1024) void scan_kernel() {
    __shared__ int wsum[32];
    const int PER = 20;   // 1000 threads * 20 = 20000
    int t = threadIdx.x;
    int lane = t & 31, w = t >> 5;
    int v[PER];
    int sum = 0;
    int base = t * PER;
    if (t < 1000) {
        #pragma unroll
        for (int i = 0; i < PER; i++) {
            sum += g_deg[base + i];
            v[i] = sum;
        }
    }
    // warp inclusive scan of per-thread totals
    int x = sum;
    #pragma unroll
    for (int off = 1; off < 32; off <<= 1) {
        int y = __shfl_up_sync(0xffffffffu, x, off);
        if (lane >= off) x += y;
    }
    if (lane == 31) wsum[w] = x;
    __syncthreads();
    if (w == 0) {
        int y = wsum[lane];
        #pragma unroll
        for (int off = 1; off < 32; off <<= 1) {
            int z = __shfl_up_sync(0xffffffffu, y, off);
            if (lane >= off) y += z;
        }
        wsum[lane] = y;
    }
    __syncthreads();
    int prefix = x - sum + (w > 0 ? wsum[w - 1] : 0);  // exclusive prefix for this thread
    if (t < 1000) {
        if (t == 0) g_rowptr[0] = 0;
        #pragma unroll
        for (int i = 0; i < PER; i++) g_rowptr[base + i + 1] = prefix + v[i];
    }
}

__global__ void scatter_kernel(const int* __restrict__ src, const int* __restrict__ dst) {
    int e = blockIdx.x * blockDim.x + threadIdx.x;
    if (e >= NE) return;
    int d = dst[e];
    int p = atomicAdd(&g_fill[d], 1);
    int pos = g_rowptr[d] + p;
    g_csrc[pos] = src[e];
    g_ceid[pos] = e;
}

// ---------------- edge embedding -> 12 logits per edge ----------------------
__global__ __launch_bounds__(256) void edge_emb_kernel(const float* __restrict__ eattr,
                                                       const int* __restrict__ dst,
                                                       const float* __restrict__ eemb_W,
                                                       const float* __restrict__ eemb_b) {
    __shared__ float sW[256];
    __shared__ float sb[64];
    __shared__ float sA[HDIM * 12];
    int t = threadIdx.x;
    if (t < 256) sW[t] = eemb_W[t];
    if (t < 64) sb[t] = eemb_b[t];
    for (int i = t; i < HDIM * 12; i += 256) sA[i] = g_weatt[i];
    __syncthreads();

    int e = blockIdx.x * blockDim.x + t;
    if (e >= NE) return;
    float4 a = *(const float4*)&eattr[e * 4];
    int dn = dst[e];
    float aed[12];
    #pragma unroll
    for (int o = 0; o < 12; o++) aed[o] = 0.f;
    #pragma unroll 4
    for (int d = 0; d < 64; d++) {
        float ea = a.x * sW[d] + a.y * sW[64 + d] + a.z * sW[128 + d] + a.w * sW[192 + d] + sb[d];
        ea = fmaxf(ea, 0.f);
        #pragma unroll
        for (int o = 0; o < 12; o++) aed[o] += ea * sA[d * 12 + o];
    }
    float* out = &g_aede[e * 12];
    *(float4*)&out[0] = make_float4(aed[0], aed[1], aed[2], aed[3]);
    *(float4*)&out[4] = make_float4(aed[4], aed[5], aed[6], aed[7]);
    *(float4*)&out[8] = make_float4(aed[8], aed[9], aed[10], aed[11]);
    #pragma unroll
    for (int o = 0; o < 12; o++) atomicAdd(&g_aeds[dn * 12 + o], aed[o]);
}

// ------- per-layer GEMM xp = h@W (20000x64 @ 64x256) + fused a_s/a_d -------
__global__ __launch_bounds__(256) void gemm_attn_kernel(const float* __restrict__ hin,
                                                        const float* __restrict__ W,
                                                        const float* __restrict__ att_src,
                                                        const float* __restrict__ att_dst) {
    __shared__ float Hs[64][65];
    __shared__ float Ws[64][64];
    int n0 = blockIdx.x * 64;
    int h = blockIdx.y;          // head == 64-col tile
    int c0 = h * 64;
    int tid = threadIdx.x;
    {
        int r = tid >> 4, q = tid & 15;
        #pragma unroll
        for (int rr = 0; rr < 64; rr += 16) {
            int row = r + rr;
            float4 v = make_float4(0.f, 0.f, 0.f, 0.f);
            if (n0 + row < NN) v = *(const float4*)&hin[(n0 + row) * HDIM + q * 4];
            Hs[row][q * 4 + 0] = v.x; Hs[row][q * 4 + 1] = v.y;
            Hs[row][q * 4 + 2] = v.z; Hs[row][q * 4 + 3] = v.w;
            float4 w = *(const float4*)&W[row * HC + c0 + q * 4];
            *(float4*)&Ws[row][q * 4] = w;
        }
    }
    __syncthreads();
    int ty = tid >> 4, tx = tid & 15;
    float acc[4][4];
    #pragma unroll
    for (int i = 0; i < 4; i++)
        #pragma unroll
        for (int j = 0; j < 4; j++) acc[i][j] = 0.f;
    #pragma unroll 8
    for (int k = 0; k < 64; k++) {
        float a0 = Hs[ty * 4 + 0][k], a1 = Hs[ty * 4 + 1][k];
        float a2 = Hs[ty * 4 + 2][k], a3 = Hs[ty * 4 + 3][k];
        float4 w = *(float4*)&Ws[k][tx * 4];
        acc[0][0] += a0 * w.x; acc[0][1] += a0 * w.y; acc[0][2] += a0 * w.z; acc[0][3] += a0 * w.w;
        acc[1][0] += a1 * w.x; acc[1][1] += a1 * w.y; acc[1][2] += a1 * w.z; acc[1][3] += a1 * w.w;
        acc[2][0] += a2 * w.x; acc[2][1] += a2 * w.y; acc[2][2] += a2 * w.z; acc[2][3] += a2 * w.w;
        acc[3][0] += a3 * w.x; acc[3][1] += a3 * w.y; acc[3][2] += a3 * w.z; acc[3][3] += a3 * w.w;
    }
    #pragma unroll
    for (int i = 0; i < 4; i++) {
        int row = n0 + ty * 4 + i;
        if (row < NN)
            *(float4*)&g_xp[row * HC + c0 + tx * 4] =
                make_float4(acc[i][0], acc[i][1], acc[i][2], acc[i][3]);
    }
    // fused epilogue: a_s[n,h] = xp[n, h*64: ] . att_src[h,:], same for a_d
    float as4[4], ad4[4];
    const float* As = att_src + h * 64 + tx * 4;
    const float* Ad = att_dst + h * 64 + tx * 4;
    #pragma unroll
    for (int j = 0; j < 4; j++) { as4[j] = As[j]; ad4[j] = Ad[j]; }
    float sp[4], dp[4];
    #pragma unroll
    for (int i = 0; i < 4; i++) {
        sp[i] = acc[i][0] * as4[0] + acc[i][1] * as4[1] + acc[i][2] * as4[2] + acc[i][3] * as4[3];
        dp[i] = acc[i][0] * ad4[0] + acc[i][1] * ad4[1] + acc[i][2] * ad4[2] + acc[i][3] * ad4[3];
    }
    #pragma unroll
    for (int off = 8; off >= 1; off >>= 1) {
        #pragma unroll
        for (int i = 0; i < 4; i++) {
            sp[i] += __shfl_xor_sync(0xffffffffu, sp[i], off);
            dp[i] += __shfl_xor_sync(0xffffffffu, dp[i], off);
        }
    }
    if (tx == 0) {
        #pragma unroll
        for (int i = 0; i < 4; i++) {
            int row = n0 + ty * 4 + i;
            if (row < NN) {
                g_as[row * 4 + h] = sp[i];
                g_ad[row * 4 + h] = dp[i];
            }
        }
    }
}

// ---- softmax (no max-shift; logits bounded) + aggregation, 1 warp/node ----
__global__ __launch_bounds__(256) void aggr_kernel(const float* __restrict__ conv_b, int layer,
                                                   float* __restrict__ hout,
                                                   const int* __restrict__ batch) {
    int warp = (blockIdx.x * blockDim.x + threadIdx.x) >> 5;
    if (warp >= NN) return;
    int lane = threadIdx.x & 31;
    int n = warp;
    int beg = g_rowptr[n], end = g_rowptr[n + 1];
    int l4 = layer * 4;

    float4 adv = *(const float4*)&g_ad[n * 4];
    float4 asl = *(const float4*)&g_as[n * 4];
    float4 aes = *(const float4*)&g_aeds[n * 12 + l4];
    float invdeg = 1.f / fmaxf((float)(end - beg), 1.f);

    float exs0 = __expf(lrelu(asl.x + adv.x + aes.x * invdeg));
    float exs1 = __expf(lrelu(asl.y + adv.y + aes.y * invdeg));
    float exs2 = __expf(lrelu(asl.z + adv.z + aes.z * invdeg));
    float exs3 = __expf(lrelu(asl.w + adv.w + aes.w * invdeg));

    float den0 = 0.f, den1 = 0.f, den2 = 0.f, den3 = 0.f;
    float acc[8];
    {
        const float* xr = g_xp + n * HC + lane;
        acc[0] = exs0 * xr[0];   acc[1] = exs0 * xr[32];
        acc[2] = exs1 * xr[64];  acc[3] = exs1 * xr[96];
        acc[4] = exs2 * xr[128]; acc[5] = exs2 * xr[160];
        acc[6] = exs3 * xr[192]; acc[7] = exs3 * xr[224];
    }
    for (int base = beg; base < end; base += 32) {
        int cnt = min(32, end - base);
        float f0 = 0.f, f1 = 0.f, f2 = 0.f, f3 = 0.f;
        int ss = 0;
        if (lane < cnt) {
            int e = base + lane;
            ss = g_csrc[e];
            int id = g_ceid[e];
            float4 av = *(const float4*)&g_as[ss * 4];
            float4 ae = *(const float4*)&g_aede[id * 12 + l4];
            f0 = __expf(lrelu(av.x + adv.x + ae.x));
            f1 = __expf(lrelu(av.y + adv.y + ae.y));
            f2 = __expf(lrelu(av.z + adv.z + ae.z));
            f3 = __expf(lrelu(av.w + adv.w + ae.w));
        }
        den0 += f0; den1 += f1; den2 += f2; den3 += f3;
        for (int t = 0; t < cnt; t++) {
            float b0 = __shfl_sync(0xffffffffu, f0, t);
            float b1 = __shfl_sync(0xffffffffu, f1, t);
            float b2 = __shfl_sync(0xffffffffu, f2, t);
            float b3 = __shfl_sync(0xffffffffu, f3, t);
            int sb = __shfl_sync(0xffffffffu, ss, t);
            const float* xr = g_xp + sb * HC + lane;
            acc[0] += b0 * xr[0];   acc[1] += b0 * xr[32];
            acc[2] += b1 * xr[64];  acc[3] += b1 * xr[96];
            acc[4] += b2 * xr[128]; acc[5] += b2 * xr[160];
            acc[6] += b3 * xr[192]; acc[7] += b3 * xr[224];
        }
    }
    #pragma unroll
    for (int off = 16; off >= 1; off >>= 1) {
        den0 += __shfl_xor_sync(0xffffffffu, den0, off);
        den1 += __shfl_xor_sync(0xffffffffu, den1, off);
        den2 += __shfl_xor_sync(0xffffffffu, den2, off);
        den3 += __shfl_xor_sync(0xffffffffu, den3, off);
    }
    den0 += exs0; den1 += exs1; den2 += exs2; den3 += exs3;

    float r0 = acc[0] / den0 + acc[2] / den1 + acc[4] / den2 + acc[6] / den3;
    float r1 = acc[1] / den0 + acc[3] / den1 + acc[5] / den2 + acc[7] / den3;
    float v0 = fmaxf(0.25f * r0 + conv_b[lane], 0.f);
    float v1 = fmaxf(0.25f * r1 + conv_b[lane + 32], 0.f);
    if (layer < 2) {
        hout[n * HDIM + lane]      = v0;
        hout[n * HDIM + lane + 32] = v1;
    } else {
        int b = batch[n];
        atomicAdd(&g_pool[b * 64 + lane], v0);
        atomicAdd(&g_pool[b * 64 + lane + 32], v1);
        if (lane == 0) atomicAdd(&g_cnt[b], 1);
    }
}

// ---------------- head MLP ---------------------------------------------------
__global__ __launch_bounds__(256) void final_kernel(const float* __restrict__ u,
                                                    const float* __restrict__ gW, const float* __restrict__ gb,
                                                    const float* __restrict__ f1W, const float* __restrict__ f1b,
                                                    const float* __restrict__ f2W, const float* __restrict__ f2b,
                                                    float* __restrict__ out) {
    __shared__ float pooled[NB * HDIM];
    __shared__ float ug[NB * HDIM];
    __shared__ float z1[NB * HDIM];
    int t = threadIdx.x;
    for (int i = t; i < NB * HDIM; i += 256) {
        int b = i >> 6, c = i & 63;
        float cnt = fmaxf((float)g_cnt[b], 1.f);
        pooled[i] = g_pool[i] / cnt;
        float s = gb[c];
        #pragma unroll
        for (int k = 0; k < 10; k++) s += u[b * 10 + k] * gW[k * 64 + c];
        ug[i] = fmaxf(s, 0.f);
    }
    __syncthreads();
    for (int i = t; i < NB * HDIM; i += 256) {
        int b = i >> 6, j = i & 63;
        float s = f1b[j];
        #pragma unroll 8
        for (int k = 0; k < 64; k++) s += pooled[b * 64 + k] * f1W[k * 64 + j];
        #pragma unroll 8
        for (int k = 0; k < 64; k++) s += ug[b * 64 + k] * f1W[(64 + k) * 64 + j];
        z1[i] = fmaxf(s, 0.f);
    }
    __syncthreads();
    if (t < NB * 2) {
        int b = t >> 1, o = t & 1;
        float s = f2b[o];
        #pragma unroll 8
        for (int k = 0; k < 64; k++) s += z1[b * 64 + k] * f2W[k * 2 + o];
        out[b * 2 + o] = s;
    }
}

// ---------------- launch ------------------------------------------------------
extern "C" void kernel_launch(void* const* d_in, const int* in_sizes, int n_in,
                              void* d_out, int out_size) {
    const float* x       = (const float*)d_in[0];
    const int*   eidx    = (const int*)d_in[1];
    const float* eattr   = (const float*)d_in[2];
    const float* u       = (const float*)d_in[3];
    const int*   batch   = (const int*)d_in[4];
    const float* node_W  = (const float*)d_in[5];
    const float* node_b  = (const float*)d_in[6];
    const float* eemb_W  = (const float*)d_in[7];
    const float* eemb_b  = (const float*)d_in[8];
    const float* lin_W   = (const float*)d_in[9];
    const float* att_src = (const float*)d_in[10];
    const float* att_dst = (const float*)d_in[11];
    const float* lin_eW  = (const float*)d_in[12];
    const float* att_e   = (const float*)d_in[13];
    const float* conv_b  = (const float*)d_in[14];
    const float* gW      = (const float*)d_in[15];
    const float* gb      = (const float*)d_in[16];
    const float* f1W     = (const float*)d_in[17];
    const float* f1b     = (const float*)d_in[18];
    const float* f2W     = (const float*)d_in[19];
    const float* f2b     = (const float*)d_in[20];
    float* out = (float*)d_out;

    const int* src = eidx;
    const int* dst = eidx + NE;

    void *p_deg, *p_fill, *p_h0, *p_h1;
    cudaGetSymbolAddress(&p_deg,  g_deg);
    cudaGetSymbolAddress(&p_fill, g_fill);
    cudaGetSymbolAddress(&p_h0,   g_h0);
    cudaGetSymbolAddress(&p_h1,   g_h1);

    cudaMemsetAsync(p_deg,  0, NN * sizeof(int));
    cudaMemsetAsync(p_fill, 0, NN * sizeof(int));

    int pre_blocks = PRE_WEATT_BLOCKS + (NN * HDIM + 255) / 256;
    pre_kernel<<<pre_blocks, 256>>>(dst, x, node_W, node_b, lin_eW, att_e);
    scan_kernel<<<1, 1024>>>();
    scatter_kernel<<<(NE + 255) / 256, 256>>>(src, dst);
    edge_emb_kernel<<<(NE + 255) / 256, 256>>>(eattr, dst, eemb_W, eemb_b);

    float* hbuf0 = (float*)p_h0;
    float* hbuf1 = (float*)p_h1;
    for (int l = 0; l < NL; l++) {
        const float* hin = (l & 1) ? hbuf1 : hbuf0;
        float* hout = (l & 1) ? hbuf0 : hbuf1;
        dim3 ggrid((NN + 63) / 64, NH);
        gemm_attn_kernel<<<ggrid, 256>>>(hin, lin_W + l * HDIM * HC,
                                         att_src + l * NH * 64, att_dst + l * NH * 64);
        aggr_kernel<<<(NN * 32 + 255) / 256, 256>>>(conv_b + l * 64, l, hout, batch);
    }
    final_kernel<<<1, 256>>>(u, gW, gb, f1W, f1b, f2W, f2b, out);
}